// round 2
// baseline (speedup 1.0000x reference)
#include <cuda_runtime.h>

// VectorQuantizer: B=32, D=64, T=8192, K=512
// in[0]: x   [B, D, T] float32
// in[1]: emb [K, D]    float32
// out:  [2, B, D, T] float32  (quantized_st, quantized) concatenated
//
// Per token (b, t): latent = argmin_k fl(fl(x2 - 2*dot(x, e_k)) + e2_k)
// (first-index wins ties, matching jnp.argmin), then
//   quantized_st = fl(x + fl(q - x)),  quantized = q  where q = emb[latent].

#define BB 32
#define DD 64
#define TT 8192
#define KK 512
#define TPB 256
#define TOK_PER_CTA 512        // 2 tokens per thread
#define NCHUNK ((BB * TT) / TOK_PER_CTA)   // 512 CTAs
#define SMEM_FLOATS (KK * DD + KK)
#define SMEM_BYTES (SMEM_FLOATS * 4)

extern __shared__ float s_dyn[];

__global__ void __launch_bounds__(TPB, 1)
vq_kernel(const float* __restrict__ x,
          const float* __restrict__ emb,
          float* __restrict__ out) {
    float* s_emb = s_dyn;           // [KK][DD]
    float* s_e2  = s_dyn + KK * DD; // [KK]
    const int tid = threadIdx.x;

    // ---- Load codebook into shared memory (32768 floats = 8192 float4) ----
    {
        const float4* e4 = reinterpret_cast<const float4*>(emb);
        float4* s4 = reinterpret_cast<float4*>(s_emb);
        #pragma unroll
        for (int i = 0; i < (KK * DD / 4) / TPB; i++)
            s4[tid + i * TPB] = e4[tid + i * TPB];
    }
    __syncthreads();

    // ---- e2[k] = sum_d emb[k][d]^2 (mul then add, rounded ops) ----
    for (int r = tid; r < KK; r += TPB) {
        const float* row = s_emb + r * DD;
        float s = 0.0f;
        #pragma unroll
        for (int d = 0; d < DD; d++)
            s = __fadd_rn(s, __fmul_rn(row[d], row[d]));
        s_e2[r] = s;
    }
    __syncthreads();

    // ---- token mapping: CTA covers 512 consecutive t within one b ----
    const int chunk = blockIdx.x;
    const long long g0 = (long long)chunk * TOK_PER_CTA;
    const int b  = (int)(g0 / TT);
    const int t0 = (int)(g0 % TT);
    const float* xbase = x + (long long)b * DD * TT;
    const int ta = t0 + tid;          // token A
    const int tc = t0 + tid + TPB;    // token B

    // ---- load x for both tokens into registers (coalesced per d-row) ----
    float xa[DD], xc[DD];
    #pragma unroll
    for (int d = 0; d < DD; d++) {
        xa[d] = xbase[(long long)d * TT + ta];
        xc[d] = xbase[(long long)d * TT + tc];
    }

    // ---- x2 (mul + add, no FMA contraction) ----
    float x2a = 0.0f, x2c = 0.0f;
    #pragma unroll
    for (int d = 0; d < DD; d++) {
        x2a = __fadd_rn(x2a, __fmul_rn(xa[d], xa[d]));
        x2c = __fadd_rn(x2c, __fmul_rn(xc[d], xc[d]));
    }

    // ---- argmin over K, 4 codes at a time ----
    float bda = 3.402823466e38f, bdc = 3.402823466e38f;
    int   bia = 0, bic = 0;

    for (int k = 0; k < KK; k += 4) {
        float a0 = 0.f, a1 = 0.f, a2 = 0.f, a3 = 0.f;
        float c0 = 0.f, c1 = 0.f, c2 = 0.f, c3 = 0.f;
        const float4* r0 = reinterpret_cast<const float4*>(s_emb + (k + 0) * DD);
        const float4* r1 = reinterpret_cast<const float4*>(s_emb + (k + 1) * DD);
        const float4* r2 = reinterpret_cast<const float4*>(s_emb + (k + 2) * DD);
        const float4* r3 = reinterpret_cast<const float4*>(s_emb + (k + 3) * DD);
        #pragma unroll
        for (int q = 0; q < DD / 4; q++) {
            const float4 e0 = r0[q];
            const float4 e1 = r1[q];
            const float4 e2v = r2[q];
            const float4 e3 = r3[q];
            const float pa0 = xa[q * 4 + 0], pa1 = xa[q * 4 + 1];
            const float pa2 = xa[q * 4 + 2], pa3 = xa[q * 4 + 3];
            const float pc0 = xc[q * 4 + 0], pc1 = xc[q * 4 + 1];
            const float pc2 = xc[q * 4 + 2], pc3 = xc[q * 4 + 3];

            a0 = fmaf(pa0, e0.x, a0); a0 = fmaf(pa1, e0.y, a0);
            a0 = fmaf(pa2, e0.z, a0); a0 = fmaf(pa3, e0.w, a0);
            a1 = fmaf(pa0, e1.x, a1); a1 = fmaf(pa1, e1.y, a1);
            a1 = fmaf(pa2, e1.z, a1); a1 = fmaf(pa3, e1.w, a1);
            a2 = fmaf(pa0, e2v.x, a2); a2 = fmaf(pa1, e2v.y, a2);
            a2 = fmaf(pa2, e2v.z, a2); a2 = fmaf(pa3, e2v.w, a2);
            a3 = fmaf(pa0, e3.x, a3); a3 = fmaf(pa1, e3.y, a3);
            a3 = fmaf(pa2, e3.z, a3); a3 = fmaf(pa3, e3.w, a3);

            c0 = fmaf(pc0, e0.x, c0); c0 = fmaf(pc1, e0.y, c0);
            c0 = fmaf(pc2, e0.z, c0); c0 = fmaf(pc3, e0.w, c0);
            c1 = fmaf(pc0, e1.x, c1); c1 = fmaf(pc1, e1.y, c1);
            c1 = fmaf(pc2, e1.z, c1); c1 = fmaf(pc3, e1.w, c1);
            c2 = fmaf(pc0, e2v.x, c2); c2 = fmaf(pc1, e2v.y, c2);
            c2 = fmaf(pc2, e2v.z, c2); c2 = fmaf(pc3, e2v.w, c2);
            c3 = fmaf(pc0, e3.x, c3); c3 = fmaf(pc1, e3.y, c3);
            c3 = fmaf(pc2, e3.z, c3); c3 = fmaf(pc3, e3.w, c3);
        }
        // dist = fl(fl(x2 - 2*xe) + e2); 2*xe is exact. Ascending k, strict <.
        const float ee0 = s_e2[k + 0], ee1 = s_e2[k + 1];
        const float ee2 = s_e2[k + 2], ee3 = s_e2[k + 3];

        float d0 = __fadd_rn(__fsub_rn(x2a, 2.0f * a0), ee0);
        if (d0 < bda) { bda = d0; bia = k + 0; }
        float d1 = __fadd_rn(__fsub_rn(x2a, 2.0f * a1), ee1);
        if (d1 < bda) { bda = d1; bia = k + 1; }
        float d2 = __fadd_rn(__fsub_rn(x2a, 2.0f * a2), ee2);
        if (d2 < bda) { bda = d2; bia = k + 2; }
        float d3 = __fadd_rn(__fsub_rn(x2a, 2.0f * a3), ee3);
        if (d3 < bda) { bda = d3; bia = k + 3; }

        float g0v = __fadd_rn(__fsub_rn(x2c, 2.0f * c0), ee0);
        if (g0v < bdc) { bdc = g0v; bic = k + 0; }
        float g1v = __fadd_rn(__fsub_rn(x2c, 2.0f * c1), ee1);
        if (g1v < bdc) { bdc = g1v; bic = k + 1; }
        float g2v = __fadd_rn(__fsub_rn(x2c, 2.0f * c2), ee2);
        if (g2v < bdc) { bdc = g2v; bic = k + 2; }
        float g3v = __fadd_rn(__fsub_rn(x2c, 2.0f * c3), ee3);
        if (g3v < bdc) { bdc = g3v; bic = k + 3; }
    }

    // ---- write outputs: [0] = straight-through, [1] = quantized ----
    float* o_st = out;
    float* o_q  = out + (long long)BB * DD * TT;
    const float* qa = s_emb + bia * DD;
    const float* qc = s_emb + bic * DD;
    const long long obase = (long long)b * DD * TT;

    #pragma unroll
    for (int d = 0; d < DD; d++) {
        const long long oa = obase + (long long)d * TT + ta;
        const long long oc = obase + (long long)d * TT + tc;
        const float q1 = qa[d];
        const float q2 = qc[d];
        // quantized_st = fl(x + fl(q - x))  (matches jnp straight-through)
        o_st[oa] = __fadd_rn(xa[d], __fsub_rn(q1, xa[d]));
        o_q[oa]  = q1;
        o_st[oc] = __fadd_rn(xc[d], __fsub_rn(q2, xc[d]));
        o_q[oc]  = q2;
    }
}

extern "C" void kernel_launch(void* const* d_in, const int* in_sizes, int n_in,
                              void* d_out, int out_size) {
    const float* x   = (const float*)d_in[0];
    const float* emb = (const float*)d_in[1];
    float* out = (float*)d_out;
    (void)in_sizes; (void)n_in; (void)out_size;

    cudaFuncSetAttribute(vq_kernel,
                         cudaFuncAttributeMaxDynamicSharedMemorySize,
                         SMEM_BYTES);
    vq_kernel<<<NCHUNK, TPB, SMEM_BYTES>>>(x, emb, out);
}

// round 5
// speedup vs baseline: 1.4834x; 1.4834x over previous
#include <cuda_runtime.h>
#include <cuda_bf16.h>
#include <cstdint>

// VectorQuantizer via mma.sync (HMMA bf16, split-precision) + exact-margin rescore.
// B=32, D=64, T=8192, K=512.

#define BB 32
#define DD 64
#define TT 8192
#define KK 512
#define NTOK (BB * TT)
#define TILE_M 128
#define NTILES (NTOK / TILE_M)      // 2048
#define TILES_PER_B (TT / TILE_M)   // 64
#define NTHREADS 256
#define GRIDX 152
#define ARRSZ ((long long)BB * DD * TT)
#define MARGIN 5e-5f
#define FINF 3.402823466e38f

// bf16 row stride: 72 elems = 144 bytes (conflict-free ldmatrix)
#define ROWS72 72
#define RSTRIDE (ROWS72 * 2)

// smem byte offsets
#define OFF_QN     0
#define OFF_REDF   32       // 8 f
#define OFF_REDK   64       // 8 i
#define OFF_E2     128      // 512 f -> 2176
#define OFF_X2     2176     // 128 f -> 2688
#define OFF_WIN    2688     // 128 i -> 3200
#define OFF_QUE    3200     // 128 i -> 3712
#define OFF_XS     3712     // 128*65*4 = 33280 -> 36992
#define OFF_XH     36992    // 128*144 = 18432 -> 55424
#define OFF_XL     55424    // 18432 -> 73856
#define OFF_QS     OFF_XH   // overlay: 64*128*4 = 32768 <= 36864 (XH+XL)
#define OFF_EH     73856    // 512*144 = 73728 -> 147584
#define OFF_EL     147584   // 73728 -> 221312
#define SMEM_TOTAL 221312
#define XS_STRIDE  65

__device__ __forceinline__ uint32_t smem_u32(const void* p) {
    uint32_t a;
    asm("{ .reg .u64 t; cvta.to.shared.u64 t, %1; cvt.u32.u64 %0, t; }" : "=r"(a) : "l"(p));
    return a;
}
__device__ __forceinline__ void ldsm_x4(uint32_t& r0, uint32_t& r1, uint32_t& r2, uint32_t& r3,
                                        uint32_t addr) {
    asm volatile("ldmatrix.sync.aligned.m8n8.x4.shared.b16 {%0,%1,%2,%3}, [%4];"
                 : "=r"(r0), "=r"(r1), "=r"(r2), "=r"(r3) : "r"(addr));
}
__device__ __forceinline__ void mma_bf16(float* c, const uint32_t* a, uint32_t b0, uint32_t b1) {
    asm volatile("mma.sync.aligned.m16n8k16.row.col.f32.bf16.bf16.f32 "
                 "{%0,%1,%2,%3}, {%4,%5,%6,%7}, {%8,%9}, {%0,%1,%2,%3};"
                 : "+f"(c[0]), "+f"(c[1]), "+f"(c[2]), "+f"(c[3])
                 : "r"(a[0]), "r"(a[1]), "r"(a[2]), "r"(a[3]), "r"(b0), "r"(b1));
}
__device__ __forceinline__ uint32_t pack_hi2(float v0, float v1, float& r0, float& r1) {
    __nv_bfloat16 h0 = __float2bfloat16_rn(v0);
    __nv_bfloat16 h1 = __float2bfloat16_rn(v1);
    r0 = __fsub_rn(v0, __bfloat162float(h0));
    r1 = __fsub_rn(v1, __bfloat162float(h1));
    return (uint32_t)__bfloat16_as_ushort(h0) | ((uint32_t)__bfloat16_as_ushort(h1) << 16);
}
__device__ __forceinline__ uint32_t pack_lo2(float r0, float r1) {
    __nv_bfloat16 l0 = __float2bfloat16_rn(r0);
    __nv_bfloat16 l1 = __float2bfloat16_rn(r1);
    return (uint32_t)__bfloat16_as_ushort(l0) | ((uint32_t)__bfloat16_as_ushort(l1) << 16);
}

extern __shared__ __align__(1024) char smem[];

__global__ void __launch_bounds__(NTHREADS, 1)
vq_mma_kernel(const float* __restrict__ x,
              const float* __restrict__ emb,
              float* __restrict__ out) {
    const int tid  = threadIdx.x;
    const int wid  = tid >> 5;
    const int lane = tid & 31;
    const uint32_t sb = smem_u32(smem);

    float* s_e2   = (float*)(smem + OFF_E2);
    float* s_x2   = (float*)(smem + OFF_X2);
    int*   s_win  = (int*)(smem + OFF_WIN);
    int*   s_que  = (int*)(smem + OFF_QUE);
    float* s_xs   = (float*)(smem + OFF_XS);
    float* s_redf = (float*)(smem + OFF_REDF);
    int*   s_redk = (int*)(smem + OFF_REDK);
    int*   s_qn   = (int*)(smem + OFF_QN);
    float* q_s    = (float*)(smem + OFF_QS);

    // ---- Prologue: codebook -> exact e2 chain + bf16 split rows [512][72] ----
    for (int r = tid; r < KK; r += NTHREADS) {
        float ev[DD];
        const float4* er = (const float4*)(emb + r * DD);
        #pragma unroll
        for (int g = 0; g < DD / 4; g++) {
            float4 v = er[g];
            ev[g*4+0] = v.x; ev[g*4+1] = v.y; ev[g*4+2] = v.z; ev[g*4+3] = v.w;
        }
        float s = 0.0f;
        #pragma unroll
        for (int d = 0; d < DD; d++) s = __fadd_rn(s, __fmul_rn(ev[d], ev[d]));
        s_e2[r] = s;
        #pragma unroll
        for (int d = 0; d < DD; d += 2) {
            float r0, r1;
            uint32_t hp = pack_hi2(ev[d], ev[d+1], r0, r1);
            uint32_t lp = pack_lo2(r0, r1);
            *(uint32_t*)(smem + OFF_EH + r * RSTRIDE + d * 2) = hp;
            *(uint32_t*)(smem + OFF_EL + r * RSTRIDE + d * 2) = lp;
        }
    }

    float* o_st = out;
    float* o_q  = out + ARRSZ;

    const int lane4 = lane & 3;
    const int laneg = lane >> 2;
    const uint32_t a_off = (uint32_t)((lane & 15) * RSTRIDE + (lane >> 4) * 16);
    const uint32_t b_off = (uint32_t)((((lane & 7) + ((lane >> 4) << 3)) * RSTRIDE) +
                                      (((lane >> 3) & 1) * 16));

    for (int tile = blockIdx.x; tile < NTILES; tile += GRIDX) {
        const int b  = tile / TILES_PER_B;
        const int t0 = (tile % TILES_PER_B) * TILE_M;
        const float* xb = x + (long long)b * DD * TT + t0;
        const long long obase = (long long)b * DD * TT;

        // ---- Phase A: load x, stage f32, exact x2 chain, bf16 split rows ----
        if (tid == 0) *s_qn = 0;
        if (tid < TILE_M) {
            const int tt = tid;
            float xv[DD];
            #pragma unroll
            for (int d = 0; d < DD; d++) xv[d] = xb[(long long)d * TT + tt];
            float s = 0.0f;
            #pragma unroll
            for (int d = 0; d < DD; d++) {
                s_xs[tt * XS_STRIDE + d] = xv[d];
                s = __fadd_rn(s, __fmul_rn(xv[d], xv[d]));
            }
            s_x2[tt] = s;
            #pragma unroll
            for (int d = 0; d < DD; d += 2) {
                float r0, r1;
                uint32_t hp = pack_hi2(xv[d], xv[d+1], r0, r1);
                uint32_t lp = pack_lo2(r0, r1);
                *(uint32_t*)(smem + OFF_XH + tt * RSTRIDE + d * 2) = hp;
                *(uint32_t*)(smem + OFF_XL + tt * RSTRIDE + d * 2) = lp;
            }
        }
        __syncthreads();

        // ---- Phase B: split-precision screen. warp w: tokens [16w,16w+16) ----
        {
            const int m0 = wid * 16;
            uint32_t ah[4][4], al[4][4];
            const uint32_t abh = sb + OFF_XH + m0 * RSTRIDE + a_off;
            const uint32_t abl = sb + OFF_XL + m0 * RSTRIDE + a_off;
            #pragma unroll
            for (int s = 0; s < 4; s++) {
                ldsm_x4(ah[s][0], ah[s][1], ah[s][2], ah[s][3], abh + s * 32);
                ldsm_x4(al[s][0], al[s][1], al[s][2], al[s][3], abl + s * 32);
            }

            float d1a = FINF, d2a = FINF, d1b = FINF, d2b = FINF;
            int   i1a = 0, i1b = 0;
            const uint32_t bbh = sb + OFF_EH + b_off;
            const uint32_t bbl = sb + OFF_EL + b_off;

            for (int c = 0; c < 8; c++) {
                const int n0 = c * 64;
                #pragma unroll
                for (int p = 0; p < 4; p++) {
                    float acc[8] = {0.f,0.f,0.f,0.f,0.f,0.f,0.f,0.f};
                    const uint32_t bth = bbh + (uint32_t)((n0 + 16 * p) * RSTRIDE);
                    const uint32_t btl = bbl + (uint32_t)((n0 + 16 * p) * RSTRIDE);
                    #pragma unroll
                    for (int s = 0; s < 4; s++) {
                        uint32_t h0, h1, h2, h3, l0, l1, l2, l3;
                        ldsm_x4(h0, h1, h2, h3, bth + s * 32);
                        ldsm_x4(l0, l1, l2, l3, btl + s * 32);
                        mma_bf16(acc,     ah[s], h0, h1);
                        mma_bf16(acc + 4, ah[s], h2, h3);
                        mma_bf16(acc,     ah[s], l0, l1);
                        mma_bf16(acc + 4, ah[s], l2, l3);
                        mma_bf16(acc,     al[s], h0, h1);
                        mma_bf16(acc + 4, al[s], h2, h3);
                    }
                    const int cb0 = n0 + 16 * p + 2 * lane4;
                    const int cb1 = cb0 + 8;
                    const float e00 = s_e2[cb0], e01 = s_e2[cb0 + 1];
                    const float e10 = s_e2[cb1], e11 = s_e2[cb1 + 1];
                    float dd;
                    dd = fmaf(-2.0f, acc[0], e00);
                    if (dd < d1a) { d2a = d1a; d1a = dd; i1a = cb0; } else if (dd < d2a) d2a = dd;
                    dd = fmaf(-2.0f, acc[1], e01);
                    if (dd < d1a) { d2a = d1a; d1a = dd; i1a = cb0 + 1; } else if (dd < d2a) d2a = dd;
                    dd = fmaf(-2.0f, acc[2], e00);
                    if (dd < d1b) { d2b = d1b; d1b = dd; i1b = cb0; } else if (dd < d2b) d2b = dd;
                    dd = fmaf(-2.0f, acc[3], e01);
                    if (dd < d1b) { d2b = d1b; d1b = dd; i1b = cb0 + 1; } else if (dd < d2b) d2b = dd;
                    dd = fmaf(-2.0f, acc[4], e10);
                    if (dd < d1a) { d2a = d1a; d1a = dd; i1a = cb1; } else if (dd < d2a) d2a = dd;
                    dd = fmaf(-2.0f, acc[5], e11);
                    if (dd < d1a) { d2a = d1a; d1a = dd; i1a = cb1 + 1; } else if (dd < d2a) d2a = dd;
                    dd = fmaf(-2.0f, acc[6], e10);
                    if (dd < d1b) { d2b = d1b; d1b = dd; i1b = cb1; } else if (dd < d2b) d2b = dd;
                    dd = fmaf(-2.0f, acc[7], e11);
                    if (dd < d1b) { d2b = d1b; d1b = dd; i1b = cb1 + 1; } else if (dd < d2b) d2b = dd;
                }
            }

            #pragma unroll
            for (int m = 1; m <= 2; m <<= 1) {
                float od = __shfl_xor_sync(0xffffffffu, d1a, m);
                int   oi = __shfl_xor_sync(0xffffffffu, i1a, m);
                float o2 = __shfl_xor_sync(0xffffffffu, d2a, m);
                bool take = (od < d1a) || (od == d1a && oi < i1a);
                float nd2 = take ? fminf(d1a, o2) : fminf(d2a, od);
                if (take) { d1a = od; i1a = oi; }
                d2a = nd2;
                od = __shfl_xor_sync(0xffffffffu, d1b, m);
                oi = __shfl_xor_sync(0xffffffffu, i1b, m);
                o2 = __shfl_xor_sync(0xffffffffu, d2b, m);
                take = (od < d1b) || (od == d1b && oi < i1b);
                nd2 = take ? fminf(d1b, o2) : fminf(d2b, od);
                if (take) { d1b = od; i1b = oi; }
                d2b = nd2;
            }
            if (lane4 == 0) {
                const int r0 = m0 + laneg, r1 = r0 + 8;
                s_win[r0] = i1a;
                if (!(d2a - d1a > MARGIN)) { int q = atomicAdd(s_qn, 1); s_que[q] = r0; }
                s_win[r1] = i1b;
                if (!(d2b - d1b > MARGIN)) { int q = atomicAdd(s_qn, 1); s_que[q] = r1; }
            }
        }
        __syncthreads();

        // ---- Phase E: exact rescore (reference chain) for ambiguous tokens ----
        {
            const int nq = *s_qn;
            for (int j = 0; j < nq; j++) {
                const int tt = s_que[j];
                const float x2t = s_x2[tt];
                float bd; int bk;
                {
                    const int k0 = tid, k1 = tid + 256;
                    const float4* e0 = (const float4*)(emb + k0 * DD);
                    const float4* e1 = (const float4*)(emb + k1 * DD);
                    float a0 = 0.0f, a1 = 0.0f;
                    #pragma unroll
                    for (int g = 0; g < DD / 4; g++) {
                        float4 v0 = __ldg(e0 + g);
                        float4 v1 = __ldg(e1 + g);
                        float p0 = s_xs[tt * XS_STRIDE + g*4 + 0];
                        float p1 = s_xs[tt * XS_STRIDE + g*4 + 1];
                        float p2 = s_xs[tt * XS_STRIDE + g*4 + 2];
                        float p3 = s_xs[tt * XS_STRIDE + g*4 + 3];
                        a0 = fmaf(p0, v0.x, a0); a0 = fmaf(p1, v0.y, a0);
                        a0 = fmaf(p2, v0.z, a0); a0 = fmaf(p3, v0.w, a0);
                        a1 = fmaf(p0, v1.x, a1); a1 = fmaf(p1, v1.y, a1);
                        a1 = fmaf(p2, v1.z, a1); a1 = fmaf(p3, v1.w, a1);
                    }
                    float dA = __fadd_rn(__fsub_rn(x2t, 2.0f * a0), s_e2[k0]);
                    float dB = __fadd_rn(__fsub_rn(x2t, 2.0f * a1), s_e2[k1]);
                    bd = dA; bk = k0;
                    if (dB < bd) { bd = dB; bk = k1; }
                }
                #pragma unroll
                for (int off = 16; off; off >>= 1) {
                    float od = __shfl_down_sync(0xFFFFFFFFu, bd, off);
                    int   ok = __shfl_down_sync(0xFFFFFFFFu, bk, off);
                    if (od < bd || (od == bd && ok < bk)) { bd = od; bk = ok; }
                }
                if (lane == 0) { s_redf[wid] = bd; s_redk[wid] = bk; }
                __syncthreads();
                if (tid == 0) {
                    float fb = s_redf[0]; int fk = s_redk[0];
                    #pragma unroll
                    for (int w = 1; w < 8; w++) {
                        float od = s_redf[w]; int ok = s_redk[w];
                        if (od < fb || (od == fb && ok < fk)) { fb = od; fk = ok; }
                    }
                    s_win[tt] = fk;
                }
                __syncthreads();
            }
        }

        // ---- Phase F: gather q rows (overlay XH/XL) then coalesced writes ----
        if (tid < TILE_M) {
            const int tt = tid;
            const int k = s_win[tt];
            const float4* er = (const float4*)(emb + k * DD);
            #pragma unroll
            for (int g = 0; g < DD / 4; g++) {
                float4 v = __ldg(er + g);
                q_s[(g*4+0) * 128 + tt] = v.x;
                q_s[(g*4+1) * 128 + tt] = v.y;
                q_s[(g*4+2) * 128 + tt] = v.z;
                q_s[(g*4+3) * 128 + tt] = v.w;
            }
        }
        __syncthreads();
        {
            #pragma unroll
            for (int it = 0; it < (64 * 64) / NTHREADS; it++) {
                const int item = tid + it * NTHREADS;
                const int d = item >> 6;
                const int p = item & 63;
                const int ti = p * 2;
                float q0 = q_s[d * 128 + ti];
                float q1 = q_s[d * 128 + ti + 1];
                float x0 = s_xs[ti * XS_STRIDE + d];
                float x1 = s_xs[(ti + 1) * XS_STRIDE + d];
                float2 stv = make_float2(__fadd_rn(x0, __fsub_rn(q0, x0)),
                                         __fadd_rn(x1, __fsub_rn(q1, x1)));
                float2 qv = make_float2(q0, q1);
                const long long o = obase + (long long)d * TT + t0 + ti;
                *(float2*)(o_st + o) = stv;
                *(float2*)(o_q + o)  = qv;
            }
        }
        __syncthreads();
    }
}

extern "C" void kernel_launch(void* const* d_in, const int* in_sizes, int n_in,
                              void* d_out, int out_size) {
    const float* x   = (const float*)d_in[0];
    const float* emb = (const float*)d_in[1];
    float* out = (float*)d_out;
    (void)in_sizes; (void)n_in; (void)out_size;

    cudaFuncSetAttribute(vq_mma_kernel,
                         cudaFuncAttributeMaxDynamicSharedMemorySize, SMEM_TOTAL);
    vq_mma_kernel<<<GRIDX, NTHREADS, SMEM_TOTAL>>>(x, emb, out);
}